// round 1
// baseline (speedup 1.0000x reference)
#include <cuda_runtime.h>

// Top-4 mean pooling: input (512, 2048, 7, 7) fp32 viewed as R=1,048,576 rows
// of 49 floats. Output R floats = sum(top4)/4 per row.
//
// Strategy: 128 threads/block, one thread per row. Block stages its 128 rows
// (128*49 = 6272 floats = 25,088 B) into shared memory with coalesced float4
// global loads, then each thread scans its row out of smem maintaining a
// sorted top-4 (a >= b >= c >= d) with a 7-op FMNMX insert chain.
// tile[t*49 + i]: 49 mod 32 = 17 (odd) -> bank-conflict-free across lanes.

#define ROW_LEN 49
#define ROWS_PER_BLOCK 128
#define TILE_FLOATS (ROWS_PER_BLOCK * ROW_LEN)   // 6272
#define TILE_F4 (TILE_FLOATS / 4)                // 1568

__global__ __launch_bounds__(ROWS_PER_BLOCK)
void apool_topk4_kernel(const float* __restrict__ in,
                        float* __restrict__ out,
                        int nrows) {
    __shared__ float tile[TILE_FLOATS];

    const int tid = threadIdx.x;
    const int block_row0 = blockIdx.x * ROWS_PER_BLOCK;
    const int rows_here = min(ROWS_PER_BLOCK, nrows - block_row0);

    // ---- Stage rows into shared memory ----
    if (rows_here == ROWS_PER_BLOCK) {
        // Full block: vectorized coalesced copy. Block base byte offset =
        // blockIdx * 25088, which is 16B-aligned.
        const float4* __restrict__ src =
            reinterpret_cast<const float4*>(in + (size_t)block_row0 * ROW_LEN);
        float4* dst = reinterpret_cast<float4*>(tile);
        #pragma unroll
        for (int i = tid; i < TILE_F4; i += ROWS_PER_BLOCK) {
            dst[i] = src[i];
        }
    } else {
        // Tail block (not hit for the benchmark shape, kept for safety).
        const int nfl = rows_here * ROW_LEN;
        const float* src = in + (size_t)block_row0 * ROW_LEN;
        for (int i = tid; i < nfl; i += ROWS_PER_BLOCK) {
            tile[i] = src[i];
        }
    }
    __syncthreads();

    // ---- Per-thread top-4 over its row ----
    const int row = block_row0 + tid;
    if (row < nrows) {
        const float* r = &tile[tid * ROW_LEN];

        // Load first 4 and sort descending (5 compare-exchanges).
        float a = r[0], b = r[1], c = r[2], d = r[3];
        float t;
        #define CE(x, y) { t = fmaxf(x, y); y = fminf(x, y); x = t; }
        CE(a, b); CE(c, d); CE(a, c); CE(b, d); CE(b, c);
        #undef CE

        // Insert remaining 45 elements: carry-down chain, 7 min/max each.
        #pragma unroll
        for (int i = 4; i < ROW_LEN; i++) {
            float v = r[i];
            float na = fmaxf(a, v); v = fminf(a, v); a = na;
            float nb = fmaxf(b, v); v = fminf(b, v); b = nb;
            float nc = fmaxf(c, v); v = fminf(c, v); c = nc;
            d = fmaxf(d, v);
        }

        out[row] = (a + b + c + d) * 0.25f;
    }
}

extern "C" void kernel_launch(void* const* d_in, const int* in_sizes, int n_in,
                              void* d_out, int out_size) {
    const float* in = (const float*)d_in[0];
    float* out = (float*)d_out;
    const int nrows = in_sizes[0] / ROW_LEN;   // 1,048,576
    const int grid = (nrows + ROWS_PER_BLOCK - 1) / ROWS_PER_BLOCK;
    apool_topk4_kernel<<<grid, ROWS_PER_BLOCK>>>(in, out, nrows);
}

// round 2
// speedup vs baseline: 1.3444x; 1.3444x over previous
#include <cuda_runtime.h>
#include <cstdint>

// Top-4 mean pooling: (512, 2048, 7, 7) fp32 -> rows of 49, out = mean(top4).
//
// Pipelined version: each block grid-strides over 96-row tiles, double-
// buffering global->shared transfers with cp.async so DRAM traffic for tile
// t+2 overlaps compute on tile t. One thread per row; sorted top-4 kept in
// registers with a 7-FMNMX insert chain.
//
// smem: 2 stages * 96 rows * 49 floats * 4B = 37,632 B (< 48KB static limit)
// -> ~6 blocks/SM (18 warps), enough to saturate the alu pipe between barriers.
// tile[t*49+i]: 49 mod 32 = 17 (odd) -> conflict-free LDS across lanes.

#define ROW_LEN 49
#define TROWS 96
#define NTHREADS 96
#define TILE_FLOATS (TROWS * ROW_LEN)     // 4704
#define NBLOCKS 888                       // 148 SMs * 6 blocks

__device__ __forceinline__ void cpa16(float* smem_dst, const float4* gsrc) {
    uint32_t s = (uint32_t)__cvta_generic_to_shared(smem_dst);
    asm volatile("cp.async.cg.shared.global [%0], [%1], 16;" :: "r"(s), "l"(gsrc));
}

__device__ __forceinline__ void issue_tile_load(const float* __restrict__ in,
                                                float* dst, int t, int ntiles,
                                                int nrows, int tid) {
    if (t < ntiles) {
        const int r0 = t * TROWS;
        const int nf4 = (min(TROWS, nrows - r0) * ROW_LEN) >> 2;  // rows%4==0 here
        const float4* src = reinterpret_cast<const float4*>(in + (size_t)r0 * ROW_LEN);
        for (int i = tid; i < nf4; i += NTHREADS)
            cpa16(dst + 4 * i, src + i);
    }
    asm volatile("cp.async.commit_group;");   // commit even if empty: keeps group count aligned
}

__global__ __launch_bounds__(NTHREADS)
void apool_topk4_pipe(const float* __restrict__ in,
                      float* __restrict__ out,
                      int nrows, int ntiles) {
    __shared__ float buf[2][TILE_FLOATS];
    const int tid = threadIdx.x;
    const int stride = gridDim.x;

    int t = blockIdx.x;
    issue_tile_load(in, buf[0], t,          ntiles, nrows, tid);
    issue_tile_load(in, buf[1], t + stride, ntiles, nrows, tid);

    int stage = 0;
    for (; t < ntiles; t += stride, stage ^= 1) {
        asm volatile("cp.async.wait_group 1;");   // oldest pending group done
        __syncthreads();                          // make it visible block-wide

        const int row = t * TROWS + tid;
        const bool valid = row < nrows;
        float res = 0.0f;
        if (valid) {
            const float* r = &buf[stage][tid * ROW_LEN];

            // Sort first 4 descending (5 compare-exchanges).
            float a = r[0], b = r[1], c = r[2], d = r[3];
            float tt;
            #define CE(x, y) { tt = fmaxf(x, y); y = fminf(x, y); x = tt; }
            CE(a, b); CE(c, d); CE(a, c); CE(b, d); CE(b, c);
            #undef CE

            // Insert remaining 45 elements: 7-op carry-down chain each.
            #pragma unroll
            for (int i = 4; i < ROW_LEN; i++) {
                float v = r[i];
                float na = fmaxf(a, v); v = fminf(a, v); a = na;
                float nb = fmaxf(b, v); v = fminf(b, v); b = nb;
                float nc = fmaxf(c, v); v = fminf(c, v); c = nc;
                d = fmaxf(d, v);
            }
            res = (a + b + c + d) * 0.25f;
        }

        __syncthreads();                          // all threads done reading buf[stage]
        issue_tile_load(in, buf[stage], t + 2 * stride, ntiles, nrows, tid);

        if (valid) out[row] = res;                // coalesced store, after next load issued
    }
}

extern "C" void kernel_launch(void* const* d_in, const int* in_sizes, int n_in,
                              void* d_out, int out_size) {
    const float* in = (const float*)d_in[0];
    float* out = (float*)d_out;
    const int nrows = in_sizes[0] / ROW_LEN;                 // 1,048,576
    const int ntiles = (nrows + TROWS - 1) / TROWS;          // 10,923
    const int grid = (ntiles < NBLOCKS) ? ntiles : NBLOCKS;
    apool_topk4_pipe<<<grid, NTHREADS>>>(in, out, nrows, ntiles);
}

// round 6
// speedup vs baseline: 1.4052x; 1.0452x over previous
#include <cuda_runtime.h>
#include <cstdint>

// Top-4 mean pooling: (512, 2048, 7, 7) fp32 -> 1,048,576 rows of 49 floats,
// out[row] = mean(top4(row)).
//
// 4-stage cp.async ring, FIXED indexing: prologue fills ALL 4 stages with
// tiles t..t+3s; each iteration waits for the oldest group (wait_group 3),
// computes the current stage, then refills that same stage with tile t+4s.
// Invariant: stage s always holds tile t + (4k+s)*stride.
//
// smem: 4 * 128 * 49 * 4B = 100,352 B dynamic -> 2 blocks/SM (8 warps).
// One thread per row; sorted top-4 via 7-FMNMX insert chain (one warp's chain
// ~saturates the 0.5 IPC/SMSP alu pipe, so 8 warps/SM suffice).
// buf[tid*49+i]: 49 mod 32 = 17 (odd) -> bank-conflict-free LDS.

#define ROW_LEN 49
#define TROWS 128
#define NTHREADS 128
#define TILE_FLOATS (TROWS * ROW_LEN)          // 6272
#define STAGES 4
#define SMEM_BYTES (STAGES * TILE_FLOATS * 4)  // 100,352
#define NBLOCKS 296                            // 148 SMs * 2 blocks

__device__ __forceinline__ void cpa16(float* smem_dst, const float4* gsrc) {
    uint32_t s = (uint32_t)__cvta_generic_to_shared(smem_dst);
    asm volatile("cp.async.cg.shared.global [%0], [%1], 16;" :: "r"(s), "l"(gsrc));
}

__device__ __forceinline__ void issue_tile_load(const float* __restrict__ in,
                                                float* dst, int t, int ntiles,
                                                int nrows, int tid) {
    if (t < ntiles) {
        const int r0 = t * TROWS;
        const int nf4 = (min(TROWS, nrows - r0) * ROW_LEN) >> 2;
        const float4* src = reinterpret_cast<const float4*>(in + (size_t)r0 * ROW_LEN);
        #pragma unroll
        for (int i = tid; i < nf4; i += NTHREADS)
            cpa16(dst + 4 * i, src + i);
    }
    asm volatile("cp.async.commit_group;");   // commit even if empty: keep group count aligned
}

__global__ __launch_bounds__(NTHREADS)
void apool_topk4_ring(const float* __restrict__ in,
                      float* __restrict__ out,
                      int nrows, int ntiles) {
    extern __shared__ float buf[];            // [STAGES][TILE_FLOATS]
    const int tid = threadIdx.x;
    const int stride = gridDim.x;

    int t = blockIdx.x;
    // Prologue: fill ALL 4 stages with tiles t .. t+3*stride.
    #pragma unroll
    for (int s = 0; s < STAGES; s++)
        issue_tile_load(in, buf + s * TILE_FLOATS, t + s * stride,
                        ntiles, nrows, tid);

    int stage = 0;
    for (; t < ntiles; t += stride) {
        asm volatile("cp.async.wait_group 3;");   // oldest of 4 groups retired
        __syncthreads();                          // block-wide visibility

        const int row = t * TROWS + tid;
        const bool valid = row < nrows;
        float res = 0.0f;
        if (valid) {
            const float* r = &buf[stage * TILE_FLOATS + tid * ROW_LEN];

            // Sort first 4 descending (5 compare-exchanges).
            float a = r[0], b = r[1], c = r[2], d = r[3];
            float tt;
            #define CE(x, y) { tt = fmaxf(x, y); y = fminf(x, y); x = tt; }
            CE(a, b); CE(c, d); CE(a, c); CE(b, d); CE(b, c);
            #undef CE

            // Insert remaining 45 elements: 7-op carry-down chain each.
            #pragma unroll
            for (int i = 4; i < ROW_LEN; i++) {
                float v = r[i];
                float na = fmaxf(a, v); v = fminf(a, v); a = na;
                float nb = fmaxf(b, v); v = fminf(b, v); b = nb;
                float nc = fmaxf(c, v); v = fminf(c, v); c = nc;
                d = fmaxf(d, v);
            }
            res = (a + b + c + d) * 0.25f;
        }

        __syncthreads();                          // everyone done reading this stage
        // Refill CURRENT stage with tile t+4*stride (next tenant of this slot).
        issue_tile_load(in, buf + stage * TILE_FLOATS, t + STAGES * stride,
                        ntiles, nrows, tid);

        if (valid) out[row] = res;                // coalesced store after load issued

        stage = (stage + 1) & (STAGES - 1);
    }
}

extern "C" void kernel_launch(void* const* d_in, const int* in_sizes, int n_in,
                              void* d_out, int out_size) {
    const float* in = (const float*)d_in[0];
    float* out = (float*)d_out;
    const int nrows = in_sizes[0] / ROW_LEN;                 // 1,048,576
    const int ntiles = (nrows + TROWS - 1) / TROWS;          // 8192
    const int grid = (ntiles < NBLOCKS) ? ntiles : NBLOCKS;

    static bool attr_set = false;
    if (!attr_set) {
        cudaFuncSetAttribute(apool_topk4_ring,
                             cudaFuncAttributeMaxDynamicSharedMemorySize,
                             SMEM_BYTES);
        attr_set = true;
    }
    apool_topk4_ring<<<grid, NTHREADS, SMEM_BYTES>>>(in, out, nrows, ntiles);
}

// round 8
// speedup vs baseline: 1.4282x; 1.0164x over previous
#include <cuda_runtime.h>
#include <cstdint>

// Top-4 mean pooling: (512, 2048, 7, 7) fp32 -> 1,048,576 rows of 49 floats,
// out[row] = mean(top4(row)).
//
// 4-stage cp.async ring + TWO THREADS PER ROW: 256 threads/block over 128-row
// tiles. Even thread scans global indices [0,24] (base row+0), odd thread
// scans [24,48] (base row+24) BUT masks its slot 0 (the overlap, global idx
// 24) to -inf in the initial sort-4 -> exact partition [0,24] U [25,48].
// Both halves run the identical unrolled 25-slot path (mask is one SEL).
//
// Pair merge (bitonic split): for desc sorted-4s A,P, A ++ reverse(P) is
// bitonic; max-half {max(a1,p4),max(a2,p3),max(a3,p2),max(a4,p1)} is the
// top-4 multiset of the union -> sum directly.
//
// smem: 4 * 128 * 49 * 4B -> 2 blocks/SM, 16 warps/SM (2x R6). Per-tile
// compute now shorter than DRAM tile delivery -> DRAM-bound.

#define ROW_LEN 49
#define TROWS 128
#define NTHREADS 256
#define TILE_FLOATS (TROWS * ROW_LEN)              // 6272
#define STAGES 4
#define SMEM_BYTES (STAGES * TILE_FLOATS * 4)      // 100,352
#define NBLOCKS 296                                // 148 SMs * 2 blocks

__device__ __forceinline__ void cpa16(float* smem_dst, const float4* gsrc) {
    uint32_t s = (uint32_t)__cvta_generic_to_shared(smem_dst);
    asm volatile("cp.async.cg.shared.global [%0], [%1], 16;" :: "r"(s), "l"(gsrc));
}

__device__ __forceinline__ void issue_tile_load(const float* __restrict__ in,
                                                float* dst, int t, int ntiles,
                                                int nrows, int tid) {
    if (t < ntiles) {
        const int r0 = t * TROWS;
        const int nf4 = (min(TROWS, nrows - r0) * ROW_LEN) >> 2;
        const float4* src = reinterpret_cast<const float4*>(in + (size_t)r0 * ROW_LEN);
        #pragma unroll
        for (int i = tid; i < nf4; i += NTHREADS)
            cpa16(dst + 4 * i, src + i);
    }
    asm volatile("cp.async.commit_group;");   // commit even if empty: keep group count aligned
}

__global__ __launch_bounds__(NTHREADS)
void apool_topk4_pair(const float* __restrict__ in,
                      float* __restrict__ out,
                      int nrows, int ntiles) {
    extern __shared__ float buf[];            // [STAGES][TILE_FLOATS]
    const int tid = threadIdx.x;
    const int stride = gridDim.x;
    const int myrow = tid >> 1;               // 0..127
    const int odd = tid & 1;                  // half selector
    const float NEG_INF = __int_as_float(0xff800000);

    int t = blockIdx.x;
    // Prologue: fill ALL 4 stages with tiles t .. t+3*stride.
    #pragma unroll
    for (int s = 0; s < STAGES; s++)
        issue_tile_load(in, buf + s * TILE_FLOATS, t + s * stride,
                        ntiles, nrows, tid);

    int stage = 0;
    for (; t < ntiles; t += stride) {
        asm volatile("cp.async.wait_group 3;");   // oldest of 4 groups retired
        __syncthreads();                          // block-wide visibility

        const int row = t * TROWS + myrow;
        const bool valid = row < nrows;
        // Half base: even -> row+0 (covers idx 0..24), odd -> row+24
        // (covers idx 24..48, with the overlap slot 0 masked below).
        const float* r = &buf[stage * TILE_FLOATS + myrow * ROW_LEN + odd * 24];

        // Sort first 4 of the half descending; odd masks slot 0 (overlap).
        float a = odd ? NEG_INF : r[0];
        float b = r[1], c = r[2], d = r[3];
        float tt;
        #define CE(x, y) { tt = fmaxf(x, y); y = fminf(x, y); x = tt; }
        CE(a, b); CE(c, d); CE(a, c); CE(b, d); CE(b, c);
        #undef CE

        // Insert slots 4..24 (7-op carry-down chain each). No masking needed.
        #pragma unroll
        for (int i = 4; i < 25; i++) {
            float v = r[i];
            float na = fmaxf(a, v); v = fminf(a, v); a = na;
            float nb = fmaxf(b, v); v = fminf(b, v); b = nb;
            float nc = fmaxf(c, v); v = fminf(c, v); c = nc;
            d = fmaxf(d, v);
        }

        // Pair merge via bitonic split: partner's sorted-4 reversed, take maxes.
        float pa = __shfl_xor_sync(0xffffffffu, a, 1);
        float pb = __shfl_xor_sync(0xffffffffu, b, 1);
        float pc = __shfl_xor_sync(0xffffffffu, c, 1);
        float pd = __shfl_xor_sync(0xffffffffu, d, 1);
        float m0 = fmaxf(a, pd);
        float m1 = fmaxf(b, pc);
        float m2 = fmaxf(c, pb);
        float m3 = fmaxf(d, pa);
        float res = (m0 + m1 + m2 + m3) * 0.25f;

        __syncthreads();                          // everyone done reading this stage
        // Refill CURRENT stage with tile t+4*stride.
        issue_tile_load(in, buf + stage * TILE_FLOATS, t + STAGES * stride,
                        ntiles, nrows, tid);

        if (valid && !odd) out[row] = res;        // even lanes: consecutive rows

        stage = (stage + 1) & (STAGES - 1);
    }
}

extern "C" void kernel_launch(void* const* d_in, const int* in_sizes, int n_in,
                              void* d_out, int out_size) {
    const float* in = (const float*)d_in[0];
    float* out = (float*)d_out;
    const int nrows = in_sizes[0] / ROW_LEN;                 // 1,048,576
    const int ntiles = (nrows + TROWS - 1) / TROWS;          // 8192
    const int grid = (ntiles < NBLOCKS) ? ntiles : NBLOCKS;

    static bool attr_set = false;
    if (!attr_set) {
        cudaFuncSetAttribute(apool_topk4_pair,
                             cudaFuncAttributeMaxDynamicSharedMemorySize,
                             SMEM_BYTES);
        attr_set = true;
    }
    apool_topk4_pair<<<grid, NTHREADS, SMEM_BYTES>>>(in, out, nrows, ntiles);
}